// round 12
// baseline (speedup 1.0000x reference)
#include <cuda_runtime.h>
#include <math.h>
#include <stdint.h>

// Problem constants
#define BSZ 2
#define SSZ 1024
#define DSZ 1024
#define HN 16
#define DK 64
#define DFF 2048
#define LN_LAYERS 4

#define LDD (LN_LAYERS * DSZ * DSZ)
#define LDF (LN_LAYERS * DSZ * DFF)

// Scratch (device globals: allocation-free)
__device__ float g_q[BSZ * SSZ * DSZ];
__device__ float g_k[BSZ * SSZ * DSZ];
__device__ float g_v[BSZ * SSZ * DSZ];
__device__ float g_o[BSZ * SSZ * DSZ];
__device__ float g_x[BSZ * SSZ * DSZ];
__device__ float g_xr[BSZ * SSZ * DSZ];     // tf32-rounded x (GEMM A input)
__device__ float g_h[BSZ * SSZ * DFF];
__device__ float g_w[3 * LDD + 2 * LDF];    // pre-rounded weights [K,N]

__device__ __forceinline__ float gelu_f(float x) {
    float x3 = x * x * x;
    float t  = tanhf(0.7978845608028654f * (x + 0.044715f * x3));
    return 0.5f * x * (1.0f + t);
}

__device__ __forceinline__ float tf32r(float x) {
    uint32_t u;
    asm("cvt.rna.tf32.f32 %0, %1;" : "=r"(u) : "f"(x));
    return __uint_as_float(u);
}
__device__ __forceinline__ float4 tf32r4(float4 v) {
    float4 t;
    t.x = tf32r(v.x); t.y = tf32r(v.y); t.z = tf32r(v.z); t.w = tf32r(v.w);
    return t;
}

__device__ __forceinline__ void ldsm4(uint32_t& r0, uint32_t& r1, uint32_t& r2,
                                      uint32_t& r3, uint32_t addr) {
    asm volatile("ldmatrix.sync.aligned.m8n8.x4.shared.b16 {%0,%1,%2,%3}, [%4];\n"
                 : "=r"(r0), "=r"(r1), "=r"(r2), "=r"(r3) : "r"(addr));
}

__device__ __forceinline__ void mma_tf32(float* d, const uint32_t* a, const uint32_t* b) {
    asm volatile(
        "mma.sync.aligned.m16n8k8.row.col.f32.tf32.tf32.f32 "
        "{%0,%1,%2,%3}, {%4,%5,%6,%7}, {%8,%9}, {%0,%1,%2,%3};\n"
        : "+f"(d[0]), "+f"(d[1]), "+f"(d[2]), "+f"(d[3])
        : "r"(a[0]), "r"(a[1]), "r"(a[2]), "r"(a[3]), "r"(b[0]), "r"(b[1]));
}

__device__ __forceinline__ void cpasync16(uint32_t dst, const void* src) {
    asm volatile("cp.async.cg.shared.global [%0], [%1], 16;\n" :: "r"(dst), "l"(src));
}
__device__ __forceinline__ void cpcommit() {
    asm volatile("cp.async.commit_group;\n" ::: "memory");
}
template<int N>
__device__ __forceinline__ void cpwait() {
    asm volatile("cp.async.wait_group %0;\n" :: "n"(N) : "memory");
}

// ---------------------------------------------------------------------------
// One-time producers: tf32-round copies
// ---------------------------------------------------------------------------
__global__ void round_copy(const float4* __restrict__ src, float4* __restrict__ dst,
                           int n4) {
    int i = blockIdx.x * blockDim.x + threadIdx.x;
    if (i < n4) dst[i] = tf32r4(src[i]);
}
__global__ void copy_and_round(const float4* __restrict__ src,
                               float4* __restrict__ xe, float4* __restrict__ xr,
                               int n4) {
    int i = blockIdx.x * blockDim.x + threadIdx.x;
    if (i < n4) {
        float4 v = src[i];
        xe[i] = v;
        xr[i] = tf32r4(v);
    }
}

// ===========================================================================
// cp.async 3-stage tf32 GEMM: C = A[M,K] @ B[K,N], pre-rounded inputs.
// 128 x BN x 32 block tile, 256 threads = 8 warps (2m x 4n), 2 blocks/SM.
// mode: 0 plain, 1 +bias[n], 2 tf32r(gelu(+bias[n])), 4 tf32r(plain).
// ===========================================================================
#define GEMM_SMEM_OF(BN) (3 * (4096 + 32 * (BN)) * 4)

template<int BN>
__global__ void __launch_bounds__(256, 2) gemm_async(
    const float* __restrict__ A,
    const float* __restrict__ B0, const float* __restrict__ B1, const float* __restrict__ B2,
    float* __restrict__ C0, float* __restrict__ C1, float* __restrict__ C2,
    int lda, int ldb, int ldc, int K,
    const float* __restrict__ bias, int mode, int qkv)
{
    constexpr int BFL = 32 * BN;              // B tile floats
    constexpr int STF = 4096 + BFL;           // stage floats
    constexpr uint32_t STB = (uint32_t)STF * 4;
    constexpr int WN  = BN / 4;               // warp n-width
    constexpr int NT  = WN / 8;               // n-tiles per warp
    constexpr int NBI = BN / 32;              // B cp.async iterations
    constexpr int RP  = 1024 / BN;            // B rows per pass

    extern __shared__ float sm[];
    const uint32_t smemBase = (uint32_t)__cvta_generic_to_shared(sm);

    const int tid = threadIdx.x, lane = tid & 31, warp = tid >> 5;
    const int wm = warp & 1, wn = warp >> 1;
    const int z = blockIdx.z;

    const float* B = B0;
    float* C = C0;
    if (qkv) {
        if (z == 1) { B = B1; C = C1; }
        else if (z == 2) { B = B2; C = C2; }
    }
    const int m0 = blockIdx.y * 128, n0 = blockIdx.x * BN;

    const int ar = tid >> 3, acq = tid & 7;
    const float* aSrc = A + (size_t)(m0 + ar) * lda + acq * 4;
    const uint32_t aDst = smemBase + (uint32_t)(ar * 32 + ((acq ^ (ar & 7)) << 2)) * 4;
    const int bk0 = tid / (BN / 4), bnq = tid % (BN / 4);
    const float* bSrc = B + (size_t)bk0 * ldb + n0 + bnq * 4;
    const uint32_t bDst = smemBase + 16384u +
                          (uint32_t)(bk0 * BN + ((bnq ^ ((bk0 & 3) << 1)) << 2)) * 4;
    const size_t ldaL = lda, ldbL = ldb;

    const int aXor = lane & 7, aHi = lane >> 4, aLo = lane & 15;
    const uint32_t aFragBase = smemBase + (uint32_t)((wm * 64 + aLo) * 32) * 4;
    const int bk = lane & 3, bn = lane >> 2;
    int bWord[NT];
#pragma unroll
    for (int nt = 0; nt < NT; nt++) {
        int n_l = wn * WN + nt * 8 + bn;
        bWord[nt] = (((n_l >> 2) ^ (bk << 1)) << 2) + (n_l & 3);
    }

    float acc[4][NT][4] = {};
    const int nIter = K >> 5;

#define G_ISSUE(S, IT)                                                     \
    {                                                                      \
        const float* as_ = aSrc + (size_t)(IT) * 32;                       \
        const float* bs_ = bSrc + (size_t)(IT) * 32 * ldbL;                \
        const uint32_t ad_ = aDst + (uint32_t)(S) * STB;                   \
        const uint32_t bd_ = bDst + (uint32_t)(S) * STB;                   \
        _Pragma("unroll")                                                  \
        for (int i_ = 0; i_ < 4; i_++)                                     \
            cpasync16(ad_ + i_ * 4096u, as_ + (size_t)i_ * 32 * ldaL);     \
        _Pragma("unroll")                                                  \
        for (int i_ = 0; i_ < NBI; i_++)                                   \
            cpasync16(bd_ + i_ * 4096u, bs_ + (size_t)i_ * RP * ldbL);     \
        cpcommit();                                                        \
    }

    G_ISSUE(0, 0);
    G_ISSUE(1, 1);

    int s = 0;
    for (int it = 0; it < nIter; it++) {
        cpwait<1>();
        __syncthreads();
        if (it + 2 < nIter) {
            int s2 = s + 2; if (s2 >= 3) s2 -= 3;
            G_ISSUE(s2, it + 2);
        } else {
            cpcommit();
        }

        const uint32_t aSB = aFragBase + (uint32_t)s * STB;
        const float* bS = sm + s * STF + 4096;
#pragma unroll
        for (int ks = 0; ks < 4; ks++) {
            const uint32_t chunkx = (uint32_t)(((ks * 2 + aHi) ^ aXor) << 4);
            uint32_t a[4][4];
#pragma unroll
            for (int mt = 0; mt < 4; mt++)
                ldsm4(a[mt][0], a[mt][1], a[mt][2], a[mt][3],
                      aSB + chunkx + (uint32_t)(mt * 16 * 32 * 4));
            uint32_t b[NT][2];
            const float* br = bS + (ks * 8 + bk) * BN;
#pragma unroll
            for (int nt = 0; nt < NT; nt++) {
                b[nt][0] = __float_as_uint(br[bWord[nt]]);
                b[nt][1] = __float_as_uint(br[bWord[nt] + 4 * BN]);
            }
#pragma unroll
            for (int mt = 0; mt < 4; mt++)
#pragma unroll
                for (int nt = 0; nt < NT; nt++)
                    mma_tf32(acc[mt][nt], a[mt], b[nt]);
        }
        s = (s + 1 == 3) ? 0 : s + 1;
    }
#undef G_ISSUE

    // epilogue
#pragma unroll
    for (int mt = 0; mt < 4; mt++) {
        const int r0 = m0 + wm * 64 + mt * 16 + (lane >> 2);
#pragma unroll
        for (int nt = 0; nt < NT; nt++) {
            const int c = n0 + wn * WN + nt * 8 + ((lane & 3) << 1);
            float v0 = acc[mt][nt][0], v1 = acc[mt][nt][1];
            float v2 = acc[mt][nt][2], v3 = acc[mt][nt][3];
            if (mode == 1) {
                float b0 = bias[c], b1 = bias[c + 1];
                v0 += b0; v1 += b1; v2 += b0; v3 += b1;
            } else if (mode == 2) {
                float b0 = bias[c], b1 = bias[c + 1];
                v0 = tf32r(gelu_f(v0 + b0)); v1 = tf32r(gelu_f(v1 + b1));
                v2 = tf32r(gelu_f(v2 + b0)); v3 = tf32r(gelu_f(v3 + b1));
            } else if (mode == 4) {
                v0 = tf32r(v0); v1 = tf32r(v1); v2 = tf32r(v2); v3 = tf32r(v3);
            }
            *(float2*)&C[(size_t)r0 * ldc + c]       = make_float2(v0, v1);
            *(float2*)&C[(size_t)(r0 + 8) * ldc + c] = make_float2(v2, v3);
        }
    }
}

// ===========================================================================
// Fused attention, 512 threads = 16 warps. Mask in static smem; bias
// prefetched into registers BEFORE the score MMA loop (latency hiding).
// ===========================================================================
#define QROWS 32
#define KTILE 128
#define SST   1028
#define QST   68
#define KST   68
#define VST   72
#define KVBUF (KTILE * VST)
#define ATTN_SMEM ((QROWS * SST + QROWS * QST + 2 * KVBUF) * 4)

__global__ void __launch_bounds__(512, 1) attn_fused(
    const float* __restrict__ q, const float* __restrict__ k,
    const float* __restrict__ v, const float* __restrict__ bias,
    const int* __restrict__ mask, float* __restrict__ p_out,
    float* __restrict__ o)
{
    extern __shared__ float sm[];
    __shared__ int msk[SSZ];
    float* Ssm  = sm;
    float* Qsm  = sm + QROWS * SST;
    float* KVsm = Qsm + QROWS * QST;

    const int tid = threadIdx.x, lane = tid & 31, w = tid >> 5;
    const int wm = w >> 3, wn = w & 7;
    const int qt = blockIdx.x, bh = blockIdx.y;
    const int b  = bh >> 4;
    const int q0 = qt * QROWS;

    const size_t xbase = (size_t)b * SSZ * DSZ + (size_t)(bh & 15) * DK;
    const float* Qg = q + xbase + (size_t)q0 * DSZ;
    const float* Kg = k + xbase;
    const float* Vg = v + xbase;
    const size_t sbase = ((size_t)bh * SSZ + q0) * SSZ;
    const float* biasg = bias + sbase;
    float* pg = p_out + sbase;

    const uint32_t SsmA  = (uint32_t)__cvta_generic_to_shared(Ssm);
    const uint32_t QsmA  = (uint32_t)__cvta_generic_to_shared(Qsm);
    const uint32_t KVsmA = (uint32_t)__cvta_generic_to_shared(KVsm);

    const int ldr = tid >> 4, ldc4 = tid & 15;

    // ---- load Q tile (pre-rounded) + mask row ----
    *(float4*)&Qsm[ldr * QST + ldc4 * 4] =
        *(const float4*)&Qg[(size_t)ldr * DSZ + ldc4 * 4];
#pragma unroll
    for (int i = tid; i < SSZ; i += 512) msk[i] = mask[b * SSZ + i];

#define ISSUE_K(BUF, KT)                                                     \
    {                                                                        \
        _Pragma("unroll")                                                    \
        for (int j_ = 0; j_ < 4; j_++) {                                     \
            int r_ = ldr + j_ * 32;                                          \
            cpasync16(KVsmA + (uint32_t)((BUF) * KVBUF + r_ * KST + ldc4 * 4) * 4, \
                      Kg + (size_t)((KT) * KTILE + r_) * DSZ + ldc4 * 4);    \
        }                                                                    \
        cpcommit();                                                          \
    }
#define ISSUE_V(BUF, KT)                                                     \
    {                                                                        \
        _Pragma("unroll")                                                    \
        for (int j_ = 0; j_ < 4; j_++) {                                     \
            int r_ = ldr + j_ * 32;                                          \
            cpasync16(KVsmA + (uint32_t)((BUF) * KVBUF + r_ * VST + ldc4 * 4) * 4, \
                      Vg + (size_t)((KT) * KTILE + r_) * DSZ + ldc4 * 4);    \
        }                                                                    \
        cpcommit();                                                          \
    }

    const int aHi = lane >> 4, aLo = lane & 15;
    const int frow = lane >> 2, fcol2 = (lane & 3) << 1;

    ISSUE_K(0, 0);
    ISSUE_K(1, 1);

    // ================= SCORES phase =================
    for (int kt = 0; kt < 8; kt++) {
        const int buf = kt & 1;
        cpwait<1>();
        __syncthreads();

        // ---- prefetch bias for this chunk (consumed after MMA loop) ----
        const int row = wm * 16 + frow;
        float2 pb0[2], pb1[2];
#pragma unroll
        for (int nt = 0; nt < 2; nt++) {
            const int col = kt * KTILE + wn * 16 + nt * 8 + fcol2;
            pb0[nt] = __ldcs((const float2*)&biasg[(size_t)row * SSZ + col]);
            pb1[nt] = __ldcs((const float2*)&biasg[(size_t)(row + 8) * SSZ + col]);
        }

        float acc[2][4] = {};
#pragma unroll
        for (int ks = 0; ks < 8; ks++) {
            const uint32_t coff = (uint32_t)((ks * 2 + aHi) << 4);
            uint32_t a[4];
            ldsm4(a[0], a[1], a[2], a[3],
                  QsmA + (uint32_t)((wm * 16 + aLo) * QST * 4) + coff);
            uint32_t bfr[2][2];
            {
                uint32_t r0, r1, r2, r3;
                ldsm4(r0, r1, r2, r3,
                      KVsmA + (uint32_t)((buf * KVBUF + (wn * 16 + aLo) * KST) * 4) + coff);
                bfr[0][0] = r0; bfr[1][0] = r1; bfr[0][1] = r2; bfr[1][1] = r3;
            }
#pragma unroll
            for (int nt = 0; nt < 2; nt++)
                mma_tf32(acc[nt], a, bfr[nt]);
        }

#pragma unroll
        for (int nt = 0; nt < 2; nt++) {
            const int col = kt * KTILE + wn * 16 + nt * 8 + fcol2;
            const int mk0 = msk[col];
            const int mk1 = msk[col + 1];
            Ssm[row * SST + col]           = mk0 ? acc[nt][0] * 0.125f + pb0[nt].x : -9e15f;
            Ssm[row * SST + col + 1]       = mk1 ? acc[nt][1] * 0.125f + pb0[nt].y : -9e15f;
            Ssm[(row + 8) * SST + col]     = mk0 ? acc[nt][2] * 0.125f + pb1[nt].x : -9e15f;
            Ssm[(row + 8) * SST + col + 1] = mk1 ? acc[nt][3] * 0.125f + pb1[nt].y : -9e15f;
        }
        __syncthreads();
        if (kt + 2 < 8) { ISSUE_K(buf, kt + 2); } else { cpcommit(); }
    }

    ISSUE_V(0, 0);
    ISSUE_V(1, 1);

    // ================= SOFTMAX phase (16 threads/row) =================
    {
        const int row = tid >> 4, sub = tid & 15;
        float4* S4 = (float4*)&Ssm[row * SST];

        float m = -INFINITY;
#pragma unroll
        for (int i = 0; i < 16; i++) {
            float4 t = S4[sub + i * 16];
            m = fmaxf(m, fmaxf(fmaxf(t.x, t.y), fmaxf(t.z, t.w)));
        }
#pragma unroll
        for (int off = 8; off; off >>= 1)
            m = fmaxf(m, __shfl_xor_sync(0xffffffffu, m, off));

        float ssum = 0.0f;
#pragma unroll
        for (int i = 0; i < 16; i++) {
            float4 t = S4[sub + i * 16];
            t.x = __expf(t.x - m); t.y = __expf(t.y - m);
            t.z = __expf(t.z - m); t.w = __expf(t.w - m);
            ssum += t.x + t.y + t.z + t.w;
            S4[sub + i * 16] = t;
        }
#pragma unroll
        for (int off = 8; off; off >>= 1)
            ssum += __shfl_xor_sync(0xffffffffu, ssum, off);
        const float inv = 1.0f / ssum;

        float4* P4g = (float4*)(pg + (size_t)row * SSZ);
#pragma unroll
        for (int i = 0; i < 16; i++) {
            float4 t = S4[sub + i * 16];
            t.x *= inv; t.y *= inv; t.z *= inv; t.w *= inv;
            __stcs(&P4g[sub + i * 16], t);
            S4[sub + i * 16] = tf32r4(t);
        }
    }

    // ================= PV phase =================
    float oacc[4] = {};

    for (int kt = 0; kt < 8; kt++) {
        const int buf = kt & 1;
        cpwait<1>();
        __syncthreads();

#pragma unroll
        for (int ks = 0; ks < 16; ks++) {
            uint32_t a[4];
            const uint32_t coff = (uint32_t)((kt * KTILE + ks * 8 + aHi * 4) << 2);
            ldsm4(a[0], a[1], a[2], a[3],
                  SsmA + (uint32_t)((wm * 16 + aLo) * SST * 4) + coff);
            uint32_t bfr[2];
            const int krow = ks * 8 + (lane & 3);
            const int d = wn * 8 + (lane >> 2);
            bfr[0] = __float_as_uint(KVsm[buf * KVBUF + krow * VST + d]);
            bfr[1] = __float_as_uint(KVsm[buf * KVBUF + (krow + 4) * VST + d]);
            mma_tf32(oacc, a, bfr);
        }
        __syncthreads();
        if (kt + 2 < 8) { ISSUE_V(buf, kt + 2); } else { cpcommit(); }
    }
#undef ISSUE_K
#undef ISSUE_V

    float* Og = o + xbase + (size_t)q0 * DSZ;
    {
        const int row = wm * 16 + frow;
        const int d = wn * 8 + fcol2;
        *(float2*)&Og[(size_t)row * DSZ + d]       = make_float2(oacc[0], oacc[1]);
        *(float2*)&Og[(size_t)(row + 8) * DSZ + d] = make_float2(oacc[2], oacc[3]);
    }
}

// ---------------------------------------------------------------------------
// Fused residual add + LayerNorm. Writes exact out AND tf32-rounded out_r.
// ---------------------------------------------------------------------------
__global__ void add_ln_kernel(const float* __restrict__ resid,
                              const float* __restrict__ add,
                              const float* __restrict__ g,
                              const float* __restrict__ bta,
                              float* __restrict__ out,
                              float* __restrict__ out_r) {
    __shared__ float sh[8];
    const size_t base = (size_t)blockIdx.x * DSZ;
    int tid = threadIdx.x, lane = tid & 31, w = tid >> 5;

    float4 a = ((const float4*)(resid + base))[tid];
    float4 b = ((const float4*)(add + base))[tid];
    float4 v = make_float4(a.x + b.x, a.y + b.y, a.z + b.z, a.w + b.w);

    float sum = v.x + v.y + v.z + v.w;
#pragma unroll
    for (int o = 16; o; o >>= 1) sum += __shfl_xor_sync(0xffffffffu, sum, o);
    if (lane == 0) sh[w] = sum;
    __syncthreads();
    float t = (lane < 8) ? sh[lane] : 0.0f;
#pragma unroll
    for (int o = 4; o; o >>= 1) t += __shfl_xor_sync(0xffffffffu, t, o);
    float mu = __shfl_sync(0xffffffffu, t, 0) * (1.0f / DSZ);

    float dx = v.x - mu, dy = v.y - mu, dz = v.z - mu, dw = v.w - mu;
    float s2 = dx * dx + dy * dy + dz * dz + dw * dw;
#pragma unroll
    for (int o = 16; o; o >>= 1) s2 += __shfl_xor_sync(0xffffffffu, s2, o);
    __syncthreads();
    if (lane == 0) sh[w] = s2;
    __syncthreads();
    float t2 = (lane < 8) ? sh[lane] : 0.0f;
#pragma unroll
    for (int o = 4; o; o >>= 1) t2 += __shfl_xor_sync(0xffffffffu, t2, o);
    float rstd = rsqrtf(__shfl_sync(0xffffffffu, t2, 0) * (1.0f / DSZ) + 1e-6f);

    float4 gg = ((const float4*)g)[tid];
    float4 bb = ((const float4*)bta)[tid];
    float4 o4 = make_float4(dx * rstd * gg.x + bb.x, dy * rstd * gg.y + bb.y,
                            dz * rstd * gg.z + bb.z, dw * rstd * gg.w + bb.w);
    ((float4*)(out + base))[tid] = o4;
    ((float4*)(out_r + base))[tid] = tf32r4(o4);
}

// ---------------------------------------------------------------------------
// Host-side orchestration (fork-join stream overlap of the pre-pass)
// ---------------------------------------------------------------------------
extern "C" void kernel_launch(void* const* d_in, const int* in_sizes, int n_in,
                              void* d_out, int out_size) {
    (void)in_sizes; (void)n_in; (void)out_size;

    const float* x_in  = (const float*)d_in[0];
    const int*   mask  = (const int*)  d_in[1];
    const float* bias  = (const float*)d_in[2];
    const float* Wq    = (const float*)d_in[3];
    const float* Wk    = (const float*)d_in[4];
    const float* Wv    = (const float*)d_in[5];
    const float* ln1g  = (const float*)d_in[6];
    const float* ln1b  = (const float*)d_in[7];
    const float* W1    = (const float*)d_in[8];
    const float* b1    = (const float*)d_in[9];
    const float* W2    = (const float*)d_in[10];
    const float* b2    = (const float*)d_in[11];
    const float* ln2g  = (const float*)d_in[12];
    const float* ln2b  = (const float*)d_in[13];
    float* out = (float*)d_out;

    float *q, *k, *v, *o, *x, *xr, *hbuf, *wbuf;
    cudaGetSymbolAddress((void**)&q, g_q);
    cudaGetSymbolAddress((void**)&k, g_k);
    cudaGetSymbolAddress((void**)&v, g_v);
    cudaGetSymbolAddress((void**)&o, g_o);
    cudaGetSymbolAddress((void**)&x, g_x);
    cudaGetSymbolAddress((void**)&xr, g_xr);
    cudaGetSymbolAddress((void**)&hbuf, g_h);
    cudaGetSymbolAddress((void**)&wbuf, g_w);

    float* WqR = wbuf;
    float* WkR = wbuf + (size_t)LDD;
    float* WvR = wbuf + (size_t)2 * LDD;
    float* W1R = wbuf + (size_t)3 * LDD;
    float* W2R = wbuf + (size_t)3 * LDD + LDF;

    const int M = BSZ * SSZ;
    const long long SL = (long long)SSZ * SSZ;
    const long long SCORES_L = (long long)BSZ * HN * SL;

    cudaFuncSetAttribute(gemm_async<128>,
                         cudaFuncAttributeMaxDynamicSharedMemorySize, GEMM_SMEM_OF(128));
    cudaFuncSetAttribute(gemm_async<64>,
                         cudaFuncAttributeMaxDynamicSharedMemorySize, GEMM_SMEM_OF(64));
    cudaFuncSetAttribute(attn_fused,
                         cudaFuncAttributeMaxDynamicSharedMemorySize, ATTN_SMEM);

    dim3 thr(256);

    // ---- fork a side stream for deferred weight rounding ----
    cudaStream_t s1;
    cudaStreamCreateWithFlags(&s1, cudaStreamNonBlocking);
    cudaEvent_t evFork, evQKVW, evFFNW;
    cudaEventCreateWithFlags(&evFork, cudaEventDisableTiming);
    cudaEventCreateWithFlags(&evQKVW, cudaEventDisableTiming);
    cudaEventCreateWithFlags(&evFFNW, cudaEventDisableTiming);

    cudaEventRecord(evFork, 0);
    cudaStreamWaitEvent(s1, evFork, 0);
    round_copy<<<LDD / 4 / 256, thr, 0, s1>>>((const float4*)Wk, (float4*)WkR, LDD / 4);
    round_copy<<<LDD / 4 / 256, thr, 0, s1>>>((const float4*)Wv, (float4*)WvR, LDD / 4);
    cudaEventRecord(evQKVW, s1);
    round_copy<<<LDF / 4 / 256, thr, 0, s1>>>((const float4*)W1, (float4*)W1R, LDF / 4);
    round_copy<<<LDF / 4 / 256, thr, 0, s1>>>((const float4*)W2, (float4*)W2R, LDF / 4);
    cudaEventRecord(evFFNW, s1);

    copy_and_round<<<M * DSZ / 4 / 256, thr>>>((const float4*)x_in, (float4*)x,
                                               (float4*)xr, M * DSZ / 4);
    round_copy<<<LDD / 4 / 256, thr>>>((const float4*)Wq, (float4*)WqR, LDD / 4);
    cudaStreamWaitEvent(0, evQKVW, 0);

    bool ffnJoined = false;
    for (int n = 0; n < LN_LAYERS; n++) {
        const float* wq = WqR + (size_t)n * DSZ * DSZ;
        const float* wk = WkR + (size_t)n * DSZ * DSZ;
        const float* wv = WvR + (size_t)n * DSZ * DSZ;
        float* sl = out + (size_t)n * SCORES_L;

        // Fused QKV (rounded outputs): z selects weight/output
        gemm_async<128><<<dim3(DSZ / 128, M / 128, 3), thr, GEMM_SMEM_OF(128)>>>(
            xr, wq, wk, wv, q, k, v, DSZ, DSZ, DSZ, DSZ, nullptr, 4, 1);

        attn_fused<<<dim3(SSZ / QROWS, BSZ * HN), dim3(512), ATTN_SMEM>>>(
            q, k, v, bias, mask, sl, o);

        add_ln_kernel<<<M, thr>>>(x, o, ln1g + n * DSZ, ln1b + n * DSZ, x, xr);

        if (!ffnJoined) {
            cudaStreamWaitEvent(0, evFFNW, 0);
            ffnJoined = true;
        }

        // FFN1 (+bias, gelu, rounded output): grid 256 blocks
        gemm_async<128><<<dim3(DFF / 128, M / 128, 1), thr, GEMM_SMEM_OF(128)>>>(
            xr, W1R + (size_t)n * DSZ * DFF, nullptr, nullptr, hbuf, nullptr, nullptr,
            DSZ, DFF, DFF, DSZ, b1 + (size_t)n * DFF, 2, 0);
        // FFN2 (+bias): BN=64 -> grid 256 blocks (was 128, half-idle chip)
        gemm_async<64><<<dim3(DSZ / 64, M / 128, 1), thr, GEMM_SMEM_OF(64)>>>(
            hbuf, W2R + (size_t)n * DFF * DSZ, nullptr, nullptr, o, nullptr, nullptr,
            DFF, DSZ, DSZ, DFF, b2 + (size_t)n * DSZ, 1, 0);

        float* xdst = (n == LN_LAYERS - 1) ? (out + (size_t)LN_LAYERS * SCORES_L) : x;
        add_ln_kernel<<<M, thr>>>(x, o, ln2g + n * DSZ, ln2b + n * DSZ, xdst, xr);
    }
}

// round 14
// speedup vs baseline: 1.0608x; 1.0608x over previous
#include <cuda_runtime.h>
#include <math.h>
#include <stdint.h>

// Problem constants
#define BSZ 2
#define SSZ 1024
#define DSZ 1024
#define HN 16
#define DK 64
#define DFF 2048
#define LN_LAYERS 4

#define LDD (LN_LAYERS * DSZ * DSZ)
#define LDF (LN_LAYERS * DSZ * DFF)

// Scratch (device globals: allocation-free)
__device__ float g_q[BSZ * SSZ * DSZ];
__device__ float g_k[BSZ * SSZ * DSZ];
__device__ float g_v[BSZ * SSZ * DSZ];
__device__ float g_o[BSZ * SSZ * DSZ];
__device__ float g_o2[BSZ * SSZ * DSZ];     // split-K partial for FFN2
__device__ float g_x[BSZ * SSZ * DSZ];
__device__ float g_xr[BSZ * SSZ * DSZ];     // tf32-rounded x (GEMM A input)
__device__ float g_h[BSZ * SSZ * DFF];
__device__ float g_w[3 * LDD + 2 * LDF];    // pre-rounded weights [K,N]

__device__ __forceinline__ float gelu_f(float x) {
    float x3 = x * x * x;
    float t  = tanhf(0.7978845608028654f * (x + 0.044715f * x3));
    return 0.5f * x * (1.0f + t);
}

__device__ __forceinline__ float tf32r(float x) {
    uint32_t u;
    asm("cvt.rna.tf32.f32 %0, %1;" : "=r"(u) : "f"(x));
    return __uint_as_float(u);
}
__device__ __forceinline__ float4 tf32r4(float4 v) {
    float4 t;
    t.x = tf32r(v.x); t.y = tf32r(v.y); t.z = tf32r(v.z); t.w = tf32r(v.w);
    return t;
}

__device__ __forceinline__ void ldsm4(uint32_t& r0, uint32_t& r1, uint32_t& r2,
                                      uint32_t& r3, uint32_t addr) {
    asm volatile("ldmatrix.sync.aligned.m8n8.x4.shared.b16 {%0,%1,%2,%3}, [%4];\n"
                 : "=r"(r0), "=r"(r1), "=r"(r2), "=r"(r3) : "r"(addr));
}

__device__ __forceinline__ void mma_tf32(float* d, const uint32_t* a, const uint32_t* b) {
    asm volatile(
        "mma.sync.aligned.m16n8k8.row.col.f32.tf32.tf32.f32 "
        "{%0,%1,%2,%3}, {%4,%5,%6,%7}, {%8,%9}, {%0,%1,%2,%3};\n"
        : "+f"(d[0]), "+f"(d[1]), "+f"(d[2]), "+f"(d[3])
        : "r"(a[0]), "r"(a[1]), "r"(a[2]), "r"(a[3]), "r"(b[0]), "r"(b[1]));
}

__device__ __forceinline__ void cpasync16(uint32_t dst, const void* src) {
    asm volatile("cp.async.cg.shared.global [%0], [%1], 16;\n" :: "r"(dst), "l"(src));
}
__device__ __forceinline__ void cpcommit() {
    asm volatile("cp.async.commit_group;\n" ::: "memory");
}
template<int N>
__device__ __forceinline__ void cpwait() {
    asm volatile("cp.async.wait_group %0;\n" :: "n"(N) : "memory");
}

// ---------------------------------------------------------------------------
// One-time producers: tf32-round copies
// ---------------------------------------------------------------------------
__global__ void round_copy(const float4* __restrict__ src, float4* __restrict__ dst,
                           int n4) {
    int i = blockIdx.x * blockDim.x + threadIdx.x;
    if (i < n4) dst[i] = tf32r4(src[i]);
}
__global__ void copy_and_round(const float4* __restrict__ src,
                               float4* __restrict__ xe, float4* __restrict__ xr,
                               int n4) {
    int i = blockIdx.x * blockDim.x + threadIdx.x;
    if (i < n4) {
        float4 v = src[i];
        xe[i] = v;
        xr[i] = tf32r4(v);
    }
}

// ===========================================================================
// cp.async 3-stage tf32 GEMM: C = A[M,K] @ B[K,N], pre-rounded inputs.
// 128x128x32 block tile, 256 threads = 8 warps (2m x 4n), 2 blocks/SM.
// qkv==1: blockIdx.z selects (B0,C0)/(B1,C1)/(B2,C2)  (fused QKV)
// qkv==2: split-K x2 -> z=0: A[:, :K]@B0 -> C0 (+bias); z=1: A[:, K:]@B1 -> C1
// mode: 0 plain, 1 +bias[n], 2 tf32r(gelu(+bias[n])), 4 tf32r(plain).
// ===========================================================================
#define GEMM_SMEM (3 * 8192 * 4)

__global__ void __launch_bounds__(256, 2) gemm_async(
    const float* __restrict__ A,
    const float* __restrict__ B0, const float* __restrict__ B1, const float* __restrict__ B2,
    float* __restrict__ C0, float* __restrict__ C1, float* __restrict__ C2,
    int lda, int ldb, int ldc, int K,
    const float* __restrict__ bias, int mode, int qkv)
{
    extern __shared__ float sm[];
    const uint32_t smemBase = (uint32_t)__cvta_generic_to_shared(sm);

    const int tid = threadIdx.x, lane = tid & 31, warp = tid >> 5;
    const int wm = warp & 1, wn = warp >> 1;
    const int z = blockIdx.z;

    const float* B = B0;
    float* C = C0;
    if (qkv == 1) {
        if (z == 1) { B = B1; C = C1; }
        else if (z == 2) { B = B2; C = C2; }
    } else if (qkv == 2) {
        if (z == 1) { B = B1; C = C1; A += K; if (mode == 1) mode = 0; }
    }
    const int m0 = blockIdx.y * 128, n0 = blockIdx.x * 128;

    const int ar = tid >> 3, acq = tid & 7;
    const float* aSrc = A + (size_t)(m0 + ar) * lda + acq * 4;
    const uint32_t aDst = smemBase + (uint32_t)(ar * 32 + ((acq ^ (ar & 7)) << 2)) * 4;
    const int bk0 = tid >> 5, bnq = tid & 31;
    const float* bSrc = B + (size_t)bk0 * ldb + n0 + bnq * 4;
    const uint32_t bDst = smemBase + 16384u +
                          (uint32_t)(bk0 * 128 + ((bnq ^ ((bk0 & 3) << 1)) << 2)) * 4;
    const size_t ldaL = lda, ldbL = ldb;

    const int aXor = lane & 7, aHi = lane >> 4, aLo = lane & 15;
    const uint32_t aFragBase = smemBase + (uint32_t)((wm * 64 + aLo) * 32) * 4;
    const int bk = lane & 3, bn = lane >> 2;
    int bWord[4];
#pragma unroll
    for (int nt = 0; nt < 4; nt++) {
        int n_l = wn * 32 + nt * 8 + bn;
        bWord[nt] = (((n_l >> 2) ^ (bk << 1)) << 2) + (n_l & 3);
    }

    float acc[4][4][4] = {};
    const int nIter = K >> 5;

#define G_ISSUE(S, IT)                                                     \
    {                                                                      \
        const float* as_ = aSrc + (size_t)(IT) * 32;                       \
        const float* bs_ = bSrc + (size_t)(IT) * 32 * ldbL;                \
        const uint32_t ad_ = aDst + (uint32_t)(S) * 32768u;                \
        const uint32_t bd_ = bDst + (uint32_t)(S) * 32768u;                \
        _Pragma("unroll")                                                  \
        for (int i_ = 0; i_ < 4; i_++)                                     \
            cpasync16(ad_ + i_ * 4096u, as_ + (size_t)i_ * 32 * ldaL);     \
        _Pragma("unroll")                                                  \
        for (int i_ = 0; i_ < 4; i_++)                                     \
            cpasync16(bd_ + i_ * 4096u, bs_ + (size_t)i_ * 8 * ldbL);      \
        cpcommit();                                                        \
    }

    G_ISSUE(0, 0);
    G_ISSUE(1, 1);

    int s = 0;
    for (int it = 0; it < nIter; it++) {
        cpwait<1>();
        __syncthreads();
        if (it + 2 < nIter) {
            int s2 = s + 2; if (s2 >= 3) s2 -= 3;
            G_ISSUE(s2, it + 2);
        } else {
            cpcommit();
        }

        const uint32_t aSB = aFragBase + (uint32_t)s * 32768u;
        const float* bS = sm + s * 8192 + 4096;
#pragma unroll
        for (int ks = 0; ks < 4; ks++) {
            const uint32_t chunkx = (uint32_t)(((ks * 2 + aHi) ^ aXor) << 4);
            uint32_t a[4][4];
#pragma unroll
            for (int mt = 0; mt < 4; mt++)
                ldsm4(a[mt][0], a[mt][1], a[mt][2], a[mt][3],
                      aSB + chunkx + (uint32_t)(mt * 16 * 32 * 4));
            uint32_t b[4][2];
            const float* br = bS + (ks * 8 + bk) * 128;
#pragma unroll
            for (int nt = 0; nt < 4; nt++) {
                b[nt][0] = __float_as_uint(br[bWord[nt]]);
                b[nt][1] = __float_as_uint(br[bWord[nt] + 512]);
            }
#pragma unroll
            for (int mt = 0; mt < 4; mt++)
#pragma unroll
                for (int nt = 0; nt < 4; nt++)
                    mma_tf32(acc[mt][nt], a[mt], b[nt]);
        }
        s = (s + 1 == 3) ? 0 : s + 1;
    }
#undef G_ISSUE

    // epilogue
#pragma unroll
    for (int mt = 0; mt < 4; mt++) {
        const int r0 = m0 + wm * 64 + mt * 16 + (lane >> 2);
#pragma unroll
        for (int nt = 0; nt < 4; nt++) {
            const int c = n0 + wn * 32 + nt * 8 + ((lane & 3) << 1);
            float v0 = acc[mt][nt][0], v1 = acc[mt][nt][1];
            float v2 = acc[mt][nt][2], v3 = acc[mt][nt][3];
            if (mode == 1) {
                float b0 = bias[c], b1 = bias[c + 1];
                v0 += b0; v1 += b1; v2 += b0; v3 += b1;
            } else if (mode == 2) {
                float b0 = bias[c], b1 = bias[c + 1];
                v0 = tf32r(gelu_f(v0 + b0)); v1 = tf32r(gelu_f(v1 + b1));
                v2 = tf32r(gelu_f(v2 + b0)); v3 = tf32r(gelu_f(v3 + b1));
            } else if (mode == 4) {
                v0 = tf32r(v0); v1 = tf32r(v1); v2 = tf32r(v2); v3 = tf32r(v3);
            }
            *(float2*)&C[(size_t)r0 * ldc + c]       = make_float2(v0, v1);
            *(float2*)&C[(size_t)(r0 + 8) * ldc + c] = make_float2(v2, v3);
        }
    }
}

// ===========================================================================
// Fused attention, 512 threads = 16 warps. Mask in static smem; bias
// prefetched into registers before the score MMA loop.
// ===========================================================================
#define QROWS 32
#define KTILE 128
#define SST   1028
#define QST   68
#define KST   68
#define VST   72
#define KVBUF (KTILE * VST)
#define ATTN_SMEM ((QROWS * SST + QROWS * QST + 2 * KVBUF) * 4)

__global__ void __launch_bounds__(512, 1) attn_fused(
    const float* __restrict__ q, const float* __restrict__ k,
    const float* __restrict__ v, const float* __restrict__ bias,
    const int* __restrict__ mask, float* __restrict__ p_out,
    float* __restrict__ o)
{
    extern __shared__ float sm[];
    __shared__ int msk[SSZ];
    float* Ssm  = sm;
    float* Qsm  = sm + QROWS * SST;
    float* KVsm = Qsm + QROWS * QST;

    const int tid = threadIdx.x, lane = tid & 31, w = tid >> 5;
    const int wm = w >> 3, wn = w & 7;
    const int qt = blockIdx.x, bh = blockIdx.y;
    const int b  = bh >> 4;
    const int q0 = qt * QROWS;

    const size_t xbase = (size_t)b * SSZ * DSZ + (size_t)(bh & 15) * DK;
    const float* Qg = q + xbase + (size_t)q0 * DSZ;
    const float* Kg = k + xbase;
    const float* Vg = v + xbase;
    const size_t sbase = ((size_t)bh * SSZ + q0) * SSZ;
    const float* biasg = bias + sbase;
    float* pg = p_out + sbase;

    const uint32_t SsmA  = (uint32_t)__cvta_generic_to_shared(Ssm);
    const uint32_t QsmA  = (uint32_t)__cvta_generic_to_shared(Qsm);
    const uint32_t KVsmA = (uint32_t)__cvta_generic_to_shared(KVsm);

    const int ldr = tid >> 4, ldc4 = tid & 15;

    *(float4*)&Qsm[ldr * QST + ldc4 * 4] =
        *(const float4*)&Qg[(size_t)ldr * DSZ + ldc4 * 4];
#pragma unroll
    for (int i = tid; i < SSZ; i += 512) msk[i] = mask[b * SSZ + i];

#define ISSUE_K(BUF, KT)                                                     \
    {                                                                        \
        _Pragma("unroll")                                                    \
        for (int j_ = 0; j_ < 4; j_++) {                                     \
            int r_ = ldr + j_ * 32;                                          \
            cpasync16(KVsmA + (uint32_t)((BUF) * KVBUF + r_ * KST + ldc4 * 4) * 4, \
                      Kg + (size_t)((KT) * KTILE + r_) * DSZ + ldc4 * 4);    \
        }                                                                    \
        cpcommit();                                                          \
    }
#define ISSUE_V(BUF, KT)                                                     \
    {                                                                        \
        _Pragma("unroll")                                                    \
        for (int j_ = 0; j_ < 4; j_++) {                                     \
            int r_ = ldr + j_ * 32;                                          \
            cpasync16(KVsmA + (uint32_t)((BUF) * KVBUF + r_ * VST + ldc4 * 4) * 4, \
                      Vg + (size_t)((KT) * KTILE + r_) * DSZ + ldc4 * 4);    \
        }                                                                    \
        cpcommit();                                                          \
    }

    const int aHi = lane >> 4, aLo = lane & 15;
    const int frow = lane >> 2, fcol2 = (lane & 3) << 1;

    ISSUE_K(0, 0);
    ISSUE_K(1, 1);

    // ================= SCORES phase =================
    for (int kt = 0; kt < 8; kt++) {
        const int buf = kt & 1;
        cpwait<1>();
        __syncthreads();

        const int row = wm * 16 + frow;
        float2 pb0[2], pb1[2];
#pragma unroll
        for (int nt = 0; nt < 2; nt++) {
            const int col = kt * KTILE + wn * 16 + nt * 8 + fcol2;
            pb0[nt] = __ldcs((const float2*)&biasg[(size_t)row * SSZ + col]);
            pb1[nt] = __ldcs((const float2*)&biasg[(size_t)(row + 8) * SSZ + col]);
        }

        float acc[2][4] = {};
#pragma unroll
        for (int ks = 0; ks < 8; ks++) {
            const uint32_t coff = (uint32_t)((ks * 2 + aHi) << 4);
            uint32_t a[4];
            ldsm4(a[0], a[1], a[2], a[3],
                  QsmA + (uint32_t)((wm * 16 + aLo) * QST * 4) + coff);
            uint32_t bfr[2][2];
            {
                uint32_t r0, r1, r2, r3;
                ldsm4(r0, r1, r2, r3,
                      KVsmA + (uint32_t)((buf * KVBUF + (wn * 16 + aLo) * KST) * 4) + coff);
                bfr[0][0] = r0; bfr[1][0] = r1; bfr[0][1] = r2; bfr[1][1] = r3;
            }
#pragma unroll
            for (int nt = 0; nt < 2; nt++)
                mma_tf32(acc[nt], a, bfr[nt]);
        }

#pragma unroll
        for (int nt = 0; nt < 2; nt++) {
            const int col = kt * KTILE + wn * 16 + nt * 8 + fcol2;
            const int mk0 = msk[col];
            const int mk1 = msk[col + 1];
            Ssm[row * SST + col]           = mk0 ? acc[nt][0] * 0.125f + pb0[nt].x : -9e15f;
            Ssm[row * SST + col + 1]       = mk1 ? acc[nt][1] * 0.125f + pb0[nt].y : -9e15f;
            Ssm[(row + 8) * SST + col]     = mk0 ? acc[nt][2] * 0.125f + pb1[nt].x : -9e15f;
            Ssm[(row + 8) * SST + col + 1] = mk1 ? acc[nt][3] * 0.125f + pb1[nt].y : -9e15f;
        }
        __syncthreads();
        if (kt + 2 < 8) { ISSUE_K(buf, kt + 2); } else { cpcommit(); }
    }

    ISSUE_V(0, 0);
    ISSUE_V(1, 1);

    // ================= SOFTMAX phase (16 threads/row) =================
    {
        const int row = tid >> 4, sub = tid & 15;
        float4* S4 = (float4*)&Ssm[row * SST];

        float m = -INFINITY;
#pragma unroll
        for (int i = 0; i < 16; i++) {
            float4 t = S4[sub + i * 16];
            m = fmaxf(m, fmaxf(fmaxf(t.x, t.y), fmaxf(t.z, t.w)));
        }
#pragma unroll
        for (int off = 8; off; off >>= 1)
            m = fmaxf(m, __shfl_xor_sync(0xffffffffu, m, off));

        float ssum = 0.0f;
#pragma unroll
        for (int i = 0; i < 16; i++) {
            float4 t = S4[sub + i * 16];
            t.x = __expf(t.x - m); t.y = __expf(t.y - m);
            t.z = __expf(t.z - m); t.w = __expf(t.w - m);
            ssum += t.x + t.y + t.z + t.w;
            S4[sub + i * 16] = t;
        }
#pragma unroll
        for (int off = 8; off; off >>= 1)
            ssum += __shfl_xor_sync(0xffffffffu, ssum, off);
        const float inv = 1.0f / ssum;

        float4* P4g = (float4*)(pg + (size_t)row * SSZ);
#pragma unroll
        for (int i = 0; i < 16; i++) {
            float4 t = S4[sub + i * 16];
            t.x *= inv; t.y *= inv; t.z *= inv; t.w *= inv;
            __stcs(&P4g[sub + i * 16], t);
            S4[sub + i * 16] = tf32r4(t);
        }
    }

    // ================= PV phase =================
    float oacc[4] = {};

    for (int kt = 0; kt < 8; kt++) {
        const int buf = kt & 1;
        cpwait<1>();
        __syncthreads();

#pragma unroll
        for (int ks = 0; ks < 16; ks++) {
            uint32_t a[4];
            const uint32_t coff = (uint32_t)((kt * KTILE + ks * 8 + aHi * 4) << 2);
            ldsm4(a[0], a[1], a[2], a[3],
                  SsmA + (uint32_t)((wm * 16 + aLo) * SST * 4) + coff);
            uint32_t bfr[2];
            const int krow = ks * 8 + (lane & 3);
            const int d = wn * 8 + (lane >> 2);
            bfr[0] = __float_as_uint(KVsm[buf * KVBUF + krow * VST + d]);
            bfr[1] = __float_as_uint(KVsm[buf * KVBUF + (krow + 4) * VST + d]);
            mma_tf32(oacc, a, bfr);
        }
        __syncthreads();
        if (kt + 2 < 8) { ISSUE_V(buf, kt + 2); } else { cpcommit(); }
    }
#undef ISSUE_K
#undef ISSUE_V

    float* Og = o + xbase + (size_t)q0 * DSZ;
    {
        const int row = wm * 16 + frow;
        const int d = wn * 8 + fcol2;
        *(float2*)&Og[(size_t)row * DSZ + d]       = make_float2(oacc[0], oacc[1]);
        *(float2*)&Og[(size_t)(row + 8) * DSZ + d] = make_float2(oacc[2], oacc[3]);
    }
}

// ---------------------------------------------------------------------------
// Fused residual add + LayerNorm (optional second addend for split-K).
// Writes exact out AND tf32-rounded out_r.
// ---------------------------------------------------------------------------
__global__ void add_ln_kernel(const float* __restrict__ resid,
                              const float* __restrict__ add,
                              const float* __restrict__ add2,
                              const float* __restrict__ g,
                              const float* __restrict__ bta,
                              float* __restrict__ out,
                              float* __restrict__ out_r) {
    __shared__ float sh[8];
    const size_t base = (size_t)blockIdx.x * DSZ;
    int tid = threadIdx.x, lane = tid & 31, w = tid >> 5;

    float4 a = ((const float4*)(resid + base))[tid];
    float4 b = ((const float4*)(add + base))[tid];
    float4 v = make_float4(a.x + b.x, a.y + b.y, a.z + b.z, a.w + b.w);
    if (add2) {
        float4 c = ((const float4*)(add2 + base))[tid];
        v.x += c.x; v.y += c.y; v.z += c.z; v.w += c.w;
    }

    float sum = v.x + v.y + v.z + v.w;
#pragma unroll
    for (int o = 16; o; o >>= 1) sum += __shfl_xor_sync(0xffffffffu, sum, o);
    if (lane == 0) sh[w] = sum;
    __syncthreads();
    float t = (lane < 8) ? sh[lane] : 0.0f;
#pragma unroll
    for (int o = 4; o; o >>= 1) t += __shfl_xor_sync(0xffffffffu, t, o);
    float mu = __shfl_sync(0xffffffffu, t, 0) * (1.0f / DSZ);

    float dx = v.x - mu, dy = v.y - mu, dz = v.z - mu, dw = v.w - mu;
    float s2 = dx * dx + dy * dy + dz * dz + dw * dw;
#pragma unroll
    for (int o = 16; o; o >>= 1) s2 += __shfl_xor_sync(0xffffffffu, s2, o);
    __syncthreads();
    if (lane == 0) sh[w] = s2;
    __syncthreads();
    float t2 = (lane < 8) ? sh[lane] : 0.0f;
#pragma unroll
    for (int o = 4; o; o >>= 1) t2 += __shfl_xor_sync(0xffffffffu, t2, o);
    float rstd = rsqrtf(__shfl_sync(0xffffffffu, t2, 0) * (1.0f / DSZ) + 1e-6f);

    float4 gg = ((const float4*)g)[tid];
    float4 bb = ((const float4*)bta)[tid];
    float4 o4 = make_float4(dx * rstd * gg.x + bb.x, dy * rstd * gg.y + bb.y,
                            dz * rstd * gg.z + bb.z, dw * rstd * gg.w + bb.w);
    ((float4*)(out + base))[tid] = o4;
    ((float4*)(out_r + base))[tid] = tf32r4(o4);
}

// ---------------------------------------------------------------------------
// Host-side orchestration (fork-join stream overlap of the pre-pass)
// ---------------------------------------------------------------------------
extern "C" void kernel_launch(void* const* d_in, const int* in_sizes, int n_in,
                              void* d_out, int out_size) {
    (void)in_sizes; (void)n_in; (void)out_size;

    const float* x_in  = (const float*)d_in[0];
    const int*   mask  = (const int*)  d_in[1];
    const float* bias  = (const float*)d_in[2];
    const float* Wq    = (const float*)d_in[3];
    const float* Wk    = (const float*)d_in[4];
    const float* Wv    = (const float*)d_in[5];
    const float* ln1g  = (const float*)d_in[6];
    const float* ln1b  = (const float*)d_in[7];
    const float* W1    = (const float*)d_in[8];
    const float* b1    = (const float*)d_in[9];
    const float* W2    = (const float*)d_in[10];
    const float* b2    = (const float*)d_in[11];
    const float* ln2g  = (const float*)d_in[12];
    const float* ln2b  = (const float*)d_in[13];
    float* out = (float*)d_out;

    float *q, *k, *v, *o, *o2, *x, *xr, *hbuf, *wbuf;
    cudaGetSymbolAddress((void**)&q, g_q);
    cudaGetSymbolAddress((void**)&k, g_k);
    cudaGetSymbolAddress((void**)&v, g_v);
    cudaGetSymbolAddress((void**)&o, g_o);
    cudaGetSymbolAddress((void**)&o2, g_o2);
    cudaGetSymbolAddress((void**)&x, g_x);
    cudaGetSymbolAddress((void**)&xr, g_xr);
    cudaGetSymbolAddress((void**)&hbuf, g_h);
    cudaGetSymbolAddress((void**)&wbuf, g_w);

    float* WqR = wbuf;
    float* WkR = wbuf + (size_t)LDD;
    float* WvR = wbuf + (size_t)2 * LDD;
    float* W1R = wbuf + (size_t)3 * LDD;
    float* W2R = wbuf + (size_t)3 * LDD + LDF;

    const int M = BSZ * SSZ;
    const long long SL = (long long)SSZ * SSZ;
    const long long SCORES_L = (long long)BSZ * HN * SL;

    cudaFuncSetAttribute(gemm_async,
                         cudaFuncAttributeMaxDynamicSharedMemorySize, GEMM_SMEM);
    cudaFuncSetAttribute(attn_fused,
                         cudaFuncAttributeMaxDynamicSharedMemorySize, ATTN_SMEM);

    dim3 thr(256);

    // ---- fork a side stream for deferred weight rounding ----
    cudaStream_t s1;
    cudaStreamCreateWithFlags(&s1, cudaStreamNonBlocking);
    cudaEvent_t evFork, evQKVW, evFFNW;
    cudaEventCreateWithFlags(&evFork, cudaEventDisableTiming);
    cudaEventCreateWithFlags(&evQKVW, cudaEventDisableTiming);
    cudaEventCreateWithFlags(&evFFNW, cudaEventDisableTiming);

    cudaEventRecord(evFork, 0);
    cudaStreamWaitEvent(s1, evFork, 0);
    round_copy<<<LDD / 4 / 256, thr, 0, s1>>>((const float4*)Wk, (float4*)WkR, LDD / 4);
    round_copy<<<LDD / 4 / 256, thr, 0, s1>>>((const float4*)Wv, (float4*)WvR, LDD / 4);
    cudaEventRecord(evQKVW, s1);
    round_copy<<<LDF / 4 / 256, thr, 0, s1>>>((const float4*)W1, (float4*)W1R, LDF / 4);
    round_copy<<<LDF / 4 / 256, thr, 0, s1>>>((const float4*)W2, (float4*)W2R, LDF / 4);
    cudaEventRecord(evFFNW, s1);

    copy_and_round<<<M * DSZ / 4 / 256, thr>>>((const float4*)x_in, (float4*)x,
                                               (float4*)xr, M * DSZ / 4);
    round_copy<<<LDD / 4 / 256, thr>>>((const float4*)Wq, (float4*)WqR, LDD / 4);
    cudaStreamWaitEvent(0, evQKVW, 0);

    bool ffnJoined = false;
    for (int n = 0; n < LN_LAYERS; n++) {
        const float* wq = WqR + (size_t)n * DSZ * DSZ;
        const float* wk = WkR + (size_t)n * DSZ * DSZ;
        const float* wv = WvR + (size_t)n * DSZ * DSZ;
        float* sl = out + (size_t)n * SCORES_L;

        // Fused QKV (rounded outputs): z selects weight/output
        gemm_async<<<dim3(DSZ / 128, M / 128, 3), thr, GEMM_SMEM>>>(
            xr, wq, wk, wv, q, k, v, DSZ, DSZ, DSZ, DSZ, nullptr, 4, 1);

        attn_fused<<<dim3(SSZ / QROWS, BSZ * HN), dim3(512), ATTN_SMEM>>>(
            q, k, v, bias, mask, sl, o);

        add_ln_kernel<<<M, thr>>>(x, o, nullptr, ln1g + n * DSZ, ln1b + n * DSZ, x, xr);

        if (!ffnJoined) {
            cudaStreamWaitEvent(0, evFFNW, 0);
            ffnJoined = true;
        }

        // FFN1 (+bias, gelu, rounded output): 256 blocks
        gemm_async<<<dim3(DFF / 128, M / 128, 1), thr, GEMM_SMEM>>>(
            xr, W1R + (size_t)n * DSZ * DFF, nullptr, nullptr, hbuf, nullptr, nullptr,
            DSZ, DFF, DFF, DSZ, b1 + (size_t)n * DFF, 2, 0);

        // FFN2 split-K x2: z=0 -> o (+bias), z=1 -> o2 ; 256 blocks total
        const float* w2a = W2R + (size_t)n * DFF * DSZ;              // rows 0..1023
        const float* w2b = w2a + (size_t)(DFF / 2) * DSZ;            // rows 1024..2047
        gemm_async<<<dim3(DSZ / 128, M / 128, 2), thr, GEMM_SMEM>>>(
            hbuf, w2a, w2b, nullptr, o, o2, nullptr,
            DFF, DSZ, DSZ, DFF / 2, b2 + (size_t)n * DSZ, 1, 2);

        float* xdst = (n == LN_LAYERS - 1) ? (out + (size_t)LN_LAYERS * SCORES_L) : x;
        add_ln_kernel<<<M, thr>>>(x, o, o2, ln2g + n * DSZ, ln2b + n * DSZ, xdst, xr);
    }
}